// round 16
// baseline (speedup 1.0000x reference)
#include <cuda_runtime.h>

// ForgetMult: h_t = f_t*x_t + (1-f_t)*h_{t-1}
// f,x: (4096, 16, 512) fp32. out inclusive, h_0 = hidden_init.
//
// Single-pass chunked scan, float4 channels, no staging; phase 4 re-reads
// f,x. vs R10 (best, kernel ~88us = ~1.0GB LTS @ ~6300 B/cyc cap):
//   - Geometry TB=128 x TILE_C4=16 -> 64KB slab/block, 3 blocks/SM
//     (192KB <= L1D carveout). Phase-1 loads use default ld.ca so the slab
//     ALLOCATES IN L1; the phase-4 re-read then hits L1 instead of L2,
//     removing ~256MB from the LTS path (the binding cap).
//   - TBLKS=32 -> look-back depth <= 31 via the 32-lane ballot wait.

#define SEQ_LEN  4096
#define C4       2048                  // float4 channels
#define SL       8                     // timesteps per thread
#define SUBS     16                    // sub-chunks per block
#define TILE_C4  16                    // f4 channels per block (64 fp32)
#define TB       (SL * SUBS)           // 128 timesteps per block
#define TBLKS    (SEQ_LEN / TB)        // 32
#define TILES    (C4 / TILE_C4)        // 128
#define NTHREADS (TILE_C4 * SUBS)      // 256

__device__ float4 g_aggA[TBLKS * C4];
__device__ float4 g_aggB[TBLKS * C4];
__device__ float4 g_prefH[C4];            // h at end of time-block 0
__device__ int    g_flag[TILES * TBLKS];  // [tile][tblk]; 0=none 1=agg 2=prefix

__device__ __forceinline__ float4 f4_fma(float4 a, float4 h, float4 b) {
    return make_float4(fmaf(a.x, h.x, b.x), fmaf(a.y, h.y, b.y),
                       fmaf(a.z, h.z, b.z), fmaf(a.w, h.w, b.w));
}
__device__ __forceinline__ float4 f4_mul(float4 a, float4 b) {
    return make_float4(a.x * b.x, a.y * b.y, a.z * b.z, a.w * b.w);
}
__device__ __forceinline__ int ld_acquire_gpu(const int* p) {
    int v;
    asm volatile("ld.acquire.gpu.global.b32 %0, [%1];" : "=r"(v) : "l"(p) : "memory");
    return v;
}
__device__ __forceinline__ void st_release_gpu(int* p, int v) {
    asm volatile("st.release.gpu.global.b32 [%0], %1;" :: "l"(p), "r"(v) : "memory");
}

__global__ void reset_flags_kernel()
{
    int i = blockIdx.x * blockDim.x + threadIdx.x;
    if (i < TILES * TBLKS) g_flag[i] = 0;
}

__global__ __launch_bounds__(NTHREADS, 3)
void forget_mult_v15_kernel(
    const float4* __restrict__ f,
    const float4* __restrict__ x,
    const float4* __restrict__ h0,
    float4* __restrict__ out)
{
    __shared__ float4 sA[SUBS * TILE_C4];
    __shared__ float4 sB[SUBS * TILE_C4];
    __shared__ float4 sHin[TILE_C4];

    const int tid  = threadIdx.x;
    const int c    = tid & (TILE_C4 - 1);       // f4 channel within tile
    const int s    = tid >> 4;                  // sub-chunk index (0..15)
    const int tile = blockIdx.x >> 5;           // / TBLKS
    const int tblk = blockIdx.x & (TBLKS - 1);  // fastest-varying in bid

    const int cg = tile * TILE_C4 + c;
    const int t0 = tblk * TB + s * SL;

    const float4* fp = f + (size_t)t0 * C4 + cg;
    const float4* xp = x + (size_t)t0 * C4 + cg;

    // ---- Phase 1: ld.ca loads (allocate in L1!), fold sub-chunk composite --
    float4 cA = make_float4(1.f, 1.f, 1.f, 1.f);
    float4 cB = make_float4(0.f, 0.f, 0.f, 0.f);
#pragma unroll
    for (int i = 0; i < SL; i++) {
        float4 ft = fp[(size_t)i * C4];    // default caching -> L1-resident
        float4 xt = xp[(size_t)i * C4];
        float4 a = make_float4(1.f - ft.x, 1.f - ft.y, 1.f - ft.z, 1.f - ft.w);
        float4 b = f4_mul(ft, xt);
        cB = f4_fma(a, cB, b);
        cA = f4_mul(cA, a);
    }

    // ---- Phase 2: Hillis-Steele over the 16 sub-chunks ----
    sA[s * TILE_C4 + c] = cA;
    sB[s * TILE_C4 + c] = cB;
    __syncthreads();
#pragma unroll
    for (int d = 1; d < SUBS; d <<= 1) {
        float4 pA, pB;
        if (s >= d) {
            pA = sA[(s - d) * TILE_C4 + c];
            pB = sB[(s - d) * TILE_C4 + c];
        }
        __syncthreads();
        if (s >= d) {
            cB = f4_fma(cA, pB, cB);   // cur ∘ prev
            cA = f4_mul(cA, pA);
            sA[s * TILE_C4 + c] = cA;
            sB[s * TILE_C4 + c] = cB;
        }
        __syncthreads();
    }
    float4 exA = make_float4(1.f, 1.f, 1.f, 1.f);
    float4 exB = make_float4(0.f, 0.f, 0.f, 0.f);
    if (s > 0) {
        exA = sA[(s - 1) * TILE_C4 + c];
        exB = sB[(s - 1) * TILE_C4 + c];
    }

    // ---- Phase 3: look-back; warp 0 lane-parallel ballot wait (tblk<=31) ----
    if (tid < 32) {
        const int lane = tid;
        float4 blkA, blkB;
        int cg0 = 0;
        if (lane < TILE_C4) {
            blkA = sA[(SUBS - 1) * TILE_C4 + lane];
            blkB = sB[(SUBS - 1) * TILE_C4 + lane];
            cg0  = tile * TILE_C4 + lane;
        }
        const int fbase = tile * TBLKS;
        if (tblk == 0) {
            if (lane < TILE_C4) {
                float4 hin0 = h0[cg0];
                g_prefH[cg0] = f4_fma(blkA, hin0, blkB);
                sHin[lane] = hin0;
            }
            __syncwarp(0xFFFFFFFFu);
            if (lane == 0)
                st_release_gpu(&g_flag[fbase + 0], 2);
        } else {
            if (lane < TILE_C4) {
                g_aggA[(size_t)tblk * C4 + cg0] = blkA;
                g_aggB[(size_t)tblk * C4 + cg0] = blkB;
            }
            __syncwarp(0xFFFFFFFFu);
            if (lane == 0)
                st_release_gpu(&g_flag[fbase + tblk], 1);

            // Parallel wait: lane j polls predecessor j; ballot collapses
            // all polls into ~1 L2 round-trip per retry.
            {
                const int need = (lane == 0) ? 2 : 1;
                bool ok;
                do {
                    ok = (lane >= tblk) ||
                         (ld_acquire_gpu(&g_flag[fbase + lane]) >= need);
                } while (!__all_sync(0xFFFFFFFFu, ok));
            }
            __syncwarp(0xFFFFFFFFu);   // order acquires before cross-lane reads

            if (lane < TILE_C4) {
                // Fold independent aggregate loads (HW-overlapped).
                float4 accA = make_float4(1.f, 1.f, 1.f, 1.f);
                float4 accB = make_float4(0.f, 0.f, 0.f, 0.f);
#pragma unroll 4
                for (int j = tblk - 1; j >= 1; j--) {
                    float4 aj = g_aggA[(size_t)j * C4 + cg0];
                    float4 bj = g_aggB[(size_t)j * C4 + cg0];
                    accB = f4_fma(accA, bj, accB);
                    accA = f4_mul(accA, aj);
                }
                float4 hpre = g_prefH[cg0];
                sHin[lane] = f4_fma(accA, hpre, accB);
            }
        }
    }
    __syncthreads();

    // ---- Phase 4: re-read f,x (L1-hot now), rebuild a,b, replay, store ----
    float4 h = f4_fma(exA, sHin[c], exB);
    float4* op = out + (size_t)t0 * C4 + cg;
#pragma unroll
    for (int i = 0; i < SL; i++) {
        float4 ft = fp[(size_t)i * C4];    // same lines as phase 1 -> L1 hit
        float4 xt = xp[(size_t)i * C4];
        float4 a = make_float4(1.f - ft.x, 1.f - ft.y, 1.f - ft.z, 1.f - ft.w);
        float4 b = f4_mul(ft, xt);
        h = f4_fma(a, h, b);
        __stcs(op + (size_t)i * C4, h);    // stores bypass L1, evict-first L2
    }
}

extern "C" void kernel_launch(void* const* d_in, const int* in_sizes, int n_in,
                              void* d_out, int out_size)
{
    const float4* f  = (const float4*)d_in[0];
    const float4* x  = (const float4*)d_in[1];
    const float4* h0 = (const float4*)d_in[2];
    float4* out = (float4*)d_out;

    static bool attr_set = false;
    if (!attr_set) {
        // Keep the smem carveout minimal so L1D gets the largest share
        // (we only need ~8.7KB smem/block; the slab residency needs 192KB).
        cudaFuncSetAttribute(forget_mult_v15_kernel,
                             cudaFuncAttributePreferredSharedMemoryCarveout, 12);
        attr_set = true;
    }

    reset_flags_kernel<<<(TILES * TBLKS + 255) / 256, 256>>>();

    dim3 grid(TILES * TBLKS);   // tblk fastest -> predecessors at lower bid
    dim3 block(NTHREADS);
    forget_mult_v15_kernel<<<grid, block>>>(f, x, h0, out);
}

// round 17
// speedup vs baseline: 1.2559x; 1.2559x over previous
#include <cuda_runtime.h>

// ForgetMult: h_t = f_t*x_t + (1-f_t)*h_{t-1}
// f,x: (4096, 16, 512) fp32. out inclusive, h_0 = hidden_init.
//
// R10 geometry (the proven winner: TB=256, TILE_C4=16, 256thr, 4 blocks/SM,
// look-back <= 15) + PARTIAL smem staging to cut LTS bytes (the measured
// binding cap ~6300 B/cyc pins the pure re-read design at ~88us kernel):
//   Phase 1 stages the within-thread inclusive prefix (A_i,B_i) for the
//   FIRST KST=6 of 16 timesteps in 48KB dynamic smem (fits 4 blocks/SM:
//   4 x 56.4KB < 228KB). Those steps skip the phase-4 L2 re-read entirely
//   (h = fma(A_i, h_sub, B_i), independent); steps 6..15 re-read from L2 as
//   before. LTS traffic 1024MB -> 928MB.

#define SEQ_LEN  4096
#define C4       2048                  // float4 channels
#define SL       16                    // timesteps per thread
#define SUBS     16                    // sub-chunks per block
#define TILE_C4  16                    // f4 channels per block (64 fp32)
#define TB       (SL * SUBS)           // 256 timesteps per block
#define TBLKS    (SEQ_LEN / TB)        // 16
#define TILES    (C4 / TILE_C4)        // 128
#define NTHREADS (TILE_C4 * SUBS)      // 256
#define KST      6                     // staged timesteps per thread

#define DSMEM_BYTES (2 * KST * SUBS * TILE_C4 * 16)   // 49152 B

__device__ float4 g_aggA[TBLKS * C4];
__device__ float4 g_aggB[TBLKS * C4];
__device__ float4 g_prefH[C4];            // h at end of time-block 0
__device__ int    g_flag[TBLKS * TILES];  // 0=none 1=agg ready 2=prefix ready

__device__ __forceinline__ float4 f4_fma(float4 a, float4 h, float4 b) {
    return make_float4(fmaf(a.x, h.x, b.x), fmaf(a.y, h.y, b.y),
                       fmaf(a.z, h.z, b.z), fmaf(a.w, h.w, b.w));
}
__device__ __forceinline__ float4 f4_mul(float4 a, float4 b) {
    return make_float4(a.x * b.x, a.y * b.y, a.z * b.z, a.w * b.w);
}
__device__ __forceinline__ int ld_acquire_gpu(const int* p) {
    int v;
    asm volatile("ld.acquire.gpu.global.b32 %0, [%1];" : "=r"(v) : "l"(p) : "memory");
    return v;
}
__device__ __forceinline__ void st_release_gpu(int* p, int v) {
    asm volatile("st.release.gpu.global.b32 [%0], %1;" :: "l"(p), "r"(v) : "memory");
}

__global__ void reset_flags_kernel()
{
    int i = blockIdx.x * blockDim.x + threadIdx.x;
    if (i < TBLKS * TILES) g_flag[i] = 0;
}

__global__ __launch_bounds__(NTHREADS, 4)
void forget_mult_v16_kernel(
    const float4* __restrict__ f,
    const float4* __restrict__ x,
    const float4* __restrict__ h0,
    float4* __restrict__ out)
{
    extern __shared__ float4 dsm[];           // staged prefix
    float4* sPA = dsm;                        // [KST][SUBS][TILE_C4]
    float4* sPB = dsm + KST * SUBS * TILE_C4;

    __shared__ float4 sA[SUBS * TILE_C4];
    __shared__ float4 sB[SUBS * TILE_C4];
    __shared__ float4 sHin[TILE_C4];

    const int tid  = threadIdx.x;
    const int c    = tid & (TILE_C4 - 1);       // f4 channel within tile
    const int s    = tid >> 4;                  // sub-chunk index (0..15)
    const int tile = blockIdx.x >> 4;           // / TBLKS
    const int tblk = blockIdx.x & (TBLKS - 1);  // fastest-varying in bid

    const int cg = tile * TILE_C4 + c;
    const int t0 = tblk * TB + s * SL;

    const float4* fp = f + (size_t)t0 * C4 + cg;
    const float4* xp = x + (size_t)t0 * C4 + cg;

    // Per-thread staged-prefix slots: [i][s][c].
    const int pslot = s * TILE_C4 + c;

    // ---- Phase 1: single pass; first KST steps stage the inclusive prefix
    //      in smem (ldcs: never re-read), rest fold only (default: stay L2) --
    float4 cA, cB;
    {
        float4 ft = __ldcs(fp);
        float4 xt = __ldcs(xp);
        cA = make_float4(1.f - ft.x, 1.f - ft.y, 1.f - ft.z, 1.f - ft.w);
        cB = f4_mul(ft, xt);
        sPA[pslot] = cA;
        sPB[pslot] = cB;
    }
#pragma unroll
    for (int i = 1; i < KST; i++) {
        float4 ft = __ldcs(fp + (size_t)i * C4);
        float4 xt = __ldcs(xp + (size_t)i * C4);
        float4 a = make_float4(1.f - ft.x, 1.f - ft.y, 1.f - ft.z, 1.f - ft.w);
        float4 b = f4_mul(ft, xt);
        cB = f4_fma(a, cB, b);                 // B_i = a_i*B_{i-1} + b_i
        cA = f4_mul(a, cA);                    // A_i = a_i*A_{i-1}
        sPA[i * SUBS * TILE_C4 + pslot] = cA;
        sPB[i * SUBS * TILE_C4 + pslot] = cB;
    }
#pragma unroll
    for (int i = KST; i < SL; i++) {
        float4 ft = fp[(size_t)i * C4];        // default: line stays in L2
        float4 xt = xp[(size_t)i * C4];
        float4 a = make_float4(1.f - ft.x, 1.f - ft.y, 1.f - ft.z, 1.f - ft.w);
        float4 b = f4_mul(ft, xt);
        cB = f4_fma(a, cB, b);
        cA = f4_mul(cA, a);
    }

    // ---- Phase 2: Hillis-Steele over the 16 sub-chunks ----
    sA[s * TILE_C4 + c] = cA;
    sB[s * TILE_C4 + c] = cB;
    __syncthreads();
#pragma unroll
    for (int d = 1; d < SUBS; d <<= 1) {
        float4 pA, pB;
        if (s >= d) {
            pA = sA[(s - d) * TILE_C4 + c];
            pB = sB[(s - d) * TILE_C4 + c];
        }
        __syncthreads();
        if (s >= d) {
            cB = f4_fma(cA, pB, cB);   // cur ∘ prev
            cA = f4_mul(cA, pA);
            sA[s * TILE_C4 + c] = cA;
            sB[s * TILE_C4 + c] = cB;
        }
        __syncthreads();
    }
    float4 exA = make_float4(1.f, 1.f, 1.f, 1.f);
    float4 exB = make_float4(0.f, 0.f, 0.f, 0.f);
    if (s > 0) {
        exA = sA[(s - 1) * TILE_C4 + c];
        exB = sB[(s - 1) * TILE_C4 + c];
    }

    // ---- Phase 3: parallel look-back (lanes 0..15 of warp 0) ----
    if (tid < TILE_C4) {
        const float4 blkA = sA[(SUBS - 1) * TILE_C4 + tid];
        const float4 blkB = sB[(SUBS - 1) * TILE_C4 + tid];
        const int cg0 = tile * TILE_C4 + tid;
        float4 hin_blk;
        if (tblk == 0) {
            hin_blk = h0[cg0];
            g_prefH[cg0] = f4_fma(blkA, hin_blk, blkB);
            __syncwarp(0x0000FFFFu);
            if (tid == 0)
                st_release_gpu(&g_flag[0 * TILES + tile], 2);
        } else {
            g_aggA[(size_t)tblk * C4 + cg0] = blkA;
            g_aggB[(size_t)tblk * C4 + cg0] = blkB;
            __syncwarp(0x0000FFFFu);
            if (tid == 0)
                st_release_gpu(&g_flag[tblk * TILES + tile], 1);

            // Wait once for all predecessors (aggs j>=1, prefix j=0).
            for (int j = tblk - 1; j >= 1; j--)
                while (ld_acquire_gpu(&g_flag[j * TILES + tile]) < 1) { }
            while (ld_acquire_gpu(&g_flag[0 * TILES + tile]) < 2) { }

            // Fold: aggregate loads independent across j -> overlapped.
            float4 accA = make_float4(1.f, 1.f, 1.f, 1.f);
            float4 accB = make_float4(0.f, 0.f, 0.f, 0.f);
#pragma unroll 5
            for (int j = tblk - 1; j >= 1; j--) {
                float4 aj = g_aggA[(size_t)j * C4 + cg0];
                float4 bj = g_aggB[(size_t)j * C4 + cg0];
                accB = f4_fma(accA, bj, accB);
                accA = f4_mul(accA, aj);
            }
            float4 hpre = g_prefH[cg0];
            hin_blk = f4_fma(accA, hpre, accB);
        }
        sHin[tid] = hin_blk;
    }
    __syncthreads();

    // ---- Phase 4: staged steps from smem (independent FMAs), then
    //      continue the chain re-reading steps KST..SL-1 from L2 ----
    const float4 hsub = f4_fma(exA, sHin[c], exB);  // h entering sub-chunk
    float4* op = out + (size_t)t0 * C4 + cg;

    float4 h = hsub;
#pragma unroll
    for (int i = 0; i < KST; i++) {
        float4 Ai = sPA[i * SUBS * TILE_C4 + pslot];
        float4 Bi = sPB[i * SUBS * TILE_C4 + pslot];
        h = f4_fma(Ai, hsub, Bi);               // independent per i
        __stcs(op + (size_t)i * C4, h);
    }
    // h now = output at step KST-1; continue serially.
#pragma unroll
    for (int i = KST; i < SL; i++) {
        float4 ft = __ldcs(fp + (size_t)i * C4);   // 2nd use: evict-first
        float4 xt = __ldcs(xp + (size_t)i * C4);
        float4 a = make_float4(1.f - ft.x, 1.f - ft.y, 1.f - ft.z, 1.f - ft.w);
        float4 b = f4_mul(ft, xt);
        h = f4_fma(a, h, b);
        __stcs(op + (size_t)i * C4, h);
    }
}

extern "C" void kernel_launch(void* const* d_in, const int* in_sizes, int n_in,
                              void* d_out, int out_size)
{
    const float4* f  = (const float4*)d_in[0];
    const float4* x  = (const float4*)d_in[1];
    const float4* h0 = (const float4*)d_in[2];
    float4* out = (float4*)d_out;

    static bool attr_set = false;
    if (!attr_set) {
        cudaFuncSetAttribute(forget_mult_v16_kernel,
                             cudaFuncAttributeMaxDynamicSharedMemorySize,
                             DSMEM_BYTES);
        attr_set = true;
    }

    reset_flags_kernel<<<(TBLKS * TILES + 255) / 256, 256>>>();

    dim3 grid(TILES * TBLKS);   // tblk fastest -> predecessors at lower bid
    dim3 block(NTHREADS);
    forget_mult_v16_kernel<<<grid, block, DSMEM_BYTES>>>(f, x, h0, out);
}